// round 10
// baseline (speedup 1.0000x reference)
#include <cuda_runtime.h>
#include <cuda_bf16.h>
#include <cstdint>

#define BATCH 16
#define LQ    512
#define LC    2048
#define DIM   1024

// ---------------------------------------------------------------------------
// Device scratch (device-side only; symbols NEVER passed from host)
// ---------------------------------------------------------------------------
__device__ float         g_attn[(size_t)BATCH * LC * LQ];     // fp32 logits
__device__ __nv_bfloat16 g_q_hi[(size_t)BATCH * LQ * DIM];
__device__ __nv_bfloat16 g_q_lo[(size_t)BATCH * LQ * DIM];
__device__ __nv_bfloat16 g_w_hi[(size_t)BATCH * LC * LQ];     // softmax weights
__device__ __nv_bfloat16 g_w_lo[(size_t)BATCH * LC * LQ];

// ---------------------------------------------------------------------------
// helpers
// ---------------------------------------------------------------------------
__device__ __forceinline__ void ldm4(uint32_t a, uint32_t& r0, uint32_t& r1,
                                     uint32_t& r2, uint32_t& r3) {
    asm volatile("ldmatrix.sync.aligned.m8n8.x4.shared.b16 {%0,%1,%2,%3}, [%4];"
                 : "=r"(r0), "=r"(r1), "=r"(r2), "=r"(r3) : "r"(a));
}
__device__ __forceinline__ void ldm4t(uint32_t a, uint32_t& r0, uint32_t& r1,
                                      uint32_t& r2, uint32_t& r3) {
    asm volatile("ldmatrix.sync.aligned.m8n8.x4.trans.shared.b16 {%0,%1,%2,%3}, [%4];"
                 : "=r"(r0), "=r"(r1), "=r"(r2), "=r"(r3) : "r"(a));
}
__device__ __forceinline__ void mma16816(float* c, uint32_t a0, uint32_t a1, uint32_t a2,
                                         uint32_t a3, uint32_t b0, uint32_t b1) {
    asm volatile(
        "mma.sync.aligned.m16n8k16.row.col.f32.bf16.bf16.f32 "
        "{%0,%1,%2,%3}, {%4,%5,%6,%7}, {%8,%9}, {%0,%1,%2,%3};"
        : "+f"(c[0]), "+f"(c[1]), "+f"(c[2]), "+f"(c[3])
        : "r"(a0), "r"(a1), "r"(a2), "r"(a3), "r"(b0), "r"(b1));
}
__device__ __forceinline__ uint32_t smem_u32(const void* p) {
    uint32_t a;
    asm("{ .reg .u64 t; cvta.to.shared.u64 t, %1; cvt.u32.u64 %0, t; }" : "=r"(a) : "l"(p));
    return a;
}
// split float4 into packed bf16 hi pair-words and lo pair-words
__device__ __forceinline__ void split4(float4 v, uint32_t& h01, uint32_t& h23,
                                       uint32_t& l01, uint32_t& l23) {
    __nv_bfloat16 hx = __float2bfloat16(v.x), hy = __float2bfloat16(v.y);
    __nv_bfloat16 hz = __float2bfloat16(v.z), hw = __float2bfloat16(v.w);
    float lx = v.x - __bfloat162float(hx), ly = v.y - __bfloat162float(hy);
    float lz = v.z - __bfloat162float(hz), lw = v.w - __bfloat162float(hw);
    __nv_bfloat162 H0(hx, hy), H1(hz, hw);
    __nv_bfloat162 L0 = __floats2bfloat162_rn(lx, ly), L1 = __floats2bfloat162_rn(lz, lw);
    h01 = *(uint32_t*)&H0; h23 = *(uint32_t*)&H1;
    l01 = *(uint32_t*)&L0; l23 = *(uint32_t*)&L1;
}

// ---------------------------------------------------------------------------
// Q pre-split: fp32 -> bf16 hi/lo (small: ~6us)
// ---------------------------------------------------------------------------
__global__ __launch_bounds__(256)
void ba_split_q(const float* __restrict__ src)
{
    const size_t i = (size_t)blockIdx.x * 256 + threadIdx.x;   // float4 index
    float4 v = ((const float4*)src)[i];
    uint32_t h01, h23, l01, l23;
    split4(v, h01, h23, l01, l23);
    ((uint2*)g_q_hi)[i] = make_uint2(h01, h23);
    ((uint2*)g_q_lo)[i] = make_uint2(l01, l23);
}

// ---------------------------------------------------------------------------
// Split-bf16 mma GEMM (R8 structure: register-prefetch LDG + STS, BK=16,
// double-buffered static smem, CTA 128x128, 8 warps 64x32).
// FIRST : logits[c][q] = ctx(fp32, split in-loop) . q(pre-split)   -> g_attn
// !FIRST: attn [c][d] = w(pre-split) . q(pre-split)  B=[k][n]      -> out right
//         + fused ctx 128x128 tile copy into out LEFT half.
// ---------------------------------------------------------------------------
#define AROWB 48                   // 16 bf16 = 32B + 16B pad (conflict-free)
#define BROWB2 272                 // GEMM2 B rows: 256B + 16B pad

template <bool FIRST>
__global__ __launch_bounds__(256)
void ba_mma(const float* __restrict__ actx, float* __restrict__ gout)
{
    constexpr int KT = FIRST ? DIM : LQ;
    constexpr int NT = KT / 16;
    constexpr int OUTSTRIDE = FIRST ? LQ : 2 * DIM;
    constexpr int OUTOFF    = FIRST ? 0  : DIM;
    constexpr int BHALF = FIRST ? (128 * AROWB) : (16 * BROWB2);   // 6144 / 4352
    constexpr int STAGE = 2 * 128 * AROWB + 2 * BHALF;             // 24576 / 20992
    constexpr int AH = 0, AL = 128 * AROWB, BH = 2 * 128 * AROWB, BL = BH + BHALF;

    __shared__ __align__(16) char sm[2 * STAGE];
    const uint32_t sb = smem_u32(sm);

    const int tid  = threadIdx.x;
    const int lane = tid & 31;
    const int warp = tid >> 5;
    const int wm   = warp & 1;         // m offset 64*wm
    const int wn   = warp >> 1;        // n offset 32*wn
    const int b  = blockIdx.z;
    const int yT = blockIdx.y;
    const int xT = blockIdx.x;

    // DEVICE-SIDE scratch binding
    const float* Abase_f = actx + ((size_t)b * LC + (size_t)yT * 128) * DIM;     // GEMM1 A
    const char*  Awh = (const char*)g_w_hi + ((size_t)b * LC + (size_t)yT * 128) * LQ * 2;
    const char*  Awl = (const char*)g_w_lo + ((size_t)b * LC + (size_t)yT * 128) * LQ * 2;
    const char*  Bqh;
    const char*  Bql;
    if (FIRST) {   // B rows = q index
        Bqh = (const char*)g_q_hi + ((size_t)b * LQ + (size_t)xT * 128) * DIM * 2;
        Bql = (const char*)g_q_lo + ((size_t)b * LQ + (size_t)xT * 128) * DIM * 2;
    } else {       // B = [k=q][n=d]
        Bqh = (const char*)g_q_hi + ((size_t)b * LQ * DIM + (size_t)xT * 128) * 2;
        Bql = (const char*)g_q_lo + ((size_t)b * LQ * DIM + (size_t)xT * 128) * 2;
    }

    // loader coordinates
    const int ar  = tid >> 2, ac  = tid & 3;          // GEMM1 A fp32: rows ar/ar+64, 16B chunk
    const int br  = tid >> 1, bc  = (tid & 1) * 16;   // bf16 [row][32B]: GEMM1 B, GEMM2 A
    const int kr2 = tid >> 4, nc2 = (tid & 15) * 16;  // GEMM2 B: 16 k-rows x 256B

    // prefetch registers
    float4 pa0, pa1;          // GEMM1 A fp32
    uint4  pah, pal;          // GEMM2 A bf16 hi/lo
    uint4  pbh, pbl;          // B bf16 hi/lo (both GEMMs)

    auto ldg_tiles = [&](int kt) {
        if (FIRST) {
            pa0 = *(const float4*)(Abase_f + (size_t)ar * DIM + kt * 16 + ac * 4);
            pa1 = *(const float4*)(Abase_f + (size_t)(ar + 64) * DIM + kt * 16 + ac * 4);
            pbh = *(const uint4*)(Bqh + (size_t)br * (DIM * 2) + kt * 32 + bc);
            pbl = *(const uint4*)(Bql + (size_t)br * (DIM * 2) + kt * 32 + bc);
        } else {
            pah = *(const uint4*)(Awh + (size_t)br * (LQ * 2) + kt * 32 + bc);
            pal = *(const uint4*)(Awl + (size_t)br * (LQ * 2) + kt * 32 + bc);
            pbh = *(const uint4*)(Bqh + (size_t)(kt * 16 + kr2) * (DIM * 2) + nc2);
            pbl = *(const uint4*)(Bql + (size_t)(kt * 16 + kr2) * (DIM * 2) + nc2);
        }
    };
    auto sts_stage = [&](uint32_t s0) {
        if (FIRST) {
            uint32_t h0, h1, l0, l1;
            split4(pa0, h0, h1, l0, l1);
            *(uint2*)(sm + (s0 + AH + ar * AROWB + ac * 8))        = make_uint2(h0, h1);
            *(uint2*)(sm + (s0 + AL + ar * AROWB + ac * 8))        = make_uint2(l0, l1);
            split4(pa1, h0, h1, l0, l1);
            *(uint2*)(sm + (s0 + AH + (ar + 64) * AROWB + ac * 8)) = make_uint2(h0, h1);
            *(uint2*)(sm + (s0 + AL + (ar + 64) * AROWB + ac * 8)) = make_uint2(l0, l1);
            *(uint4*)(sm + (s0 + BH + br * AROWB + bc)) = pbh;
            *(uint4*)(sm + (s0 + BL + br * AROWB + bc)) = pbl;
        } else {
            *(uint4*)(sm + (s0 + AH + br * AROWB + bc))    = pah;
            *(uint4*)(sm + (s0 + AL + br * AROWB + bc))    = pal;
            *(uint4*)(sm + (s0 + BH + kr2 * BROWB2 + nc2)) = pbh;
            *(uint4*)(sm + (s0 + BL + kr2 * BROWB2 + nc2)) = pbl;
        }
    };

    float acc[4][4][4];
#pragma unroll
    for (int m = 0; m < 4; m++)
#pragma unroll
        for (int n = 0; n < 4; n++)
#pragma unroll
            for (int j = 0; j < 4; j++) acc[m][n][j] = 0.f;

    // prologue: stage 0
    ldg_tiles(0);
    sts_stage(0);
    __syncthreads();

    const int lrow = lane & 15;
    const int lkb  = lane & 16;         // second 16B chunk (k+8 / n+8)
    constexpr int I1 = FIRST ? 2 : 1;   // ntile0 second b-reg
    constexpr int J0 = FIRST ? 1 : 2;   // ntile1 first b-reg

    for (int kt = 0; kt < NT; kt++) {
        const uint32_t s0 = (kt & 1) * STAGE;

        if (kt + 1 < NT) ldg_tiles(kt + 1);

        uint32_t ah[4][4], al[4][4];
#pragma unroll
        for (int mt = 0; mt < 4; mt++) {
            uint32_t ra = sb + s0 + AH + (wm * 64 + mt * 16 + lrow) * AROWB + lkb;
            ldm4(ra, ah[mt][0], ah[mt][1], ah[mt][2], ah[mt][3]);
            uint32_t rl = sb + s0 + AL + (wm * 64 + mt * 16 + lrow) * AROWB + lkb;
            ldm4(rl, al[mt][0], al[mt][1], al[mt][2], al[mt][3]);
        }
#pragma unroll
        for (int p = 0; p < 2; p++) {
            uint32_t bh[4], bl[4];
            if (FIRST) {
                uint32_t rb = sb + s0 + BH + (wn * 32 + p * 16 + lrow) * AROWB + lkb;
                ldm4(rb, bh[0], bh[1], bh[2], bh[3]);
                uint32_t rc = sb + s0 + BL + (wn * 32 + p * 16 + lrow) * AROWB + lkb;
                ldm4(rc, bl[0], bl[1], bl[2], bl[3]);
            } else {
                uint32_t rb = sb + s0 + BH + lrow * BROWB2 + (wn * 32 + p * 16) * 2 + lkb;
                ldm4t(rb, bh[0], bh[1], bh[2], bh[3]);
                uint32_t rc = sb + s0 + BL + lrow * BROWB2 + (wn * 32 + p * 16) * 2 + lkb;
                ldm4t(rc, bl[0], bl[1], bl[2], bl[3]);
            }
#pragma unroll
            for (int mt = 0; mt < 4; mt++) {
                mma16816(acc[mt][2 * p],     ah[mt][0], ah[mt][1], ah[mt][2], ah[mt][3], bh[0],  bh[I1]);
                mma16816(acc[mt][2 * p + 1], ah[mt][0], ah[mt][1], ah[mt][2], ah[mt][3], bh[J0], bh[3]);
                mma16816(acc[mt][2 * p],     al[mt][0], al[mt][1], al[mt][2], al[mt][3], bh[0],  bh[I1]);
                mma16816(acc[mt][2 * p + 1], al[mt][0], al[mt][1], al[mt][2], al[mt][3], bh[J0], bh[3]);
                mma16816(acc[mt][2 * p],     ah[mt][0], ah[mt][1], ah[mt][2], ah[mt][3], bl[0],  bl[I1]);
                mma16816(acc[mt][2 * p + 1], ah[mt][0], ah[mt][1], ah[mt][2], ah[mt][3], bl[J0], bl[3]);
            }
        }

        if (kt + 1 < NT) sts_stage(((kt + 1) & 1) * STAGE);
        __syncthreads();
    }

    // epilogue (standard m16n8 C layout)
    float* Cg = FIRST ? (float*)g_attn : gout;
    const size_t rbase = (size_t)b * LC + (size_t)yT * 128 + wm * 64 + (lane >> 2);
    const int    cbase = OUTOFF + xT * 128 + wn * 32 + (lane & 3) * 2;
#pragma unroll
    for (int mt = 0; mt < 4; mt++) {
#pragma unroll
        for (int nt = 0; nt < 4; nt++) {
            size_t r0 = (rbase + mt * 16) * OUTSTRIDE + cbase + nt * 8;
            *(float2*)(Cg + r0)                    = make_float2(acc[mt][nt][0], acc[mt][nt][1]);
            *(float2*)(Cg + r0 + 8ull * OUTSTRIDE) = make_float2(acc[mt][nt][2], acc[mt][nt][3]);
        }
    }

    // fused ctx copy into out LEFT half (GEMM2 only)
    if (!FIRST) {
        const float4* csrc = (const float4*)(actx + ((size_t)b * LC + (size_t)yT * 128) * DIM
                                             + (size_t)xT * 128);
        float4* cdst = (float4*)(gout + ((size_t)b * LC + (size_t)yT * 128) * (2 * DIM)
                                 + (size_t)xT * 128);
        const int crow = tid >> 5;
        const int ccol = tid & 31;
#pragma unroll
        for (int it = 0; it < 16; it++) {
            cdst[(size_t)(crow + it * 8) * (2 * DIM / 4) + ccol] =
                csrc[(size_t)(crow + it * 8) * (DIM / 4) + ccol];
        }
    }
}

// ---------------------------------------------------------------------------
// Warp-per-row softmax over 512 logits: fp32 in (g_attn), bf16 hi/lo out (g_w).
// ---------------------------------------------------------------------------
__global__ __launch_bounds__(256)
void ba_softmax(void)
{
    const int wid = threadIdx.x >> 5, lane = threadIdx.x & 31;
    const size_t row = (size_t)blockIdx.x * 8 + wid;
    const float4* p = (const float4*)(g_attn + row * LQ);

    float4 v[4];
    float mx = -1e30f;
#pragma unroll
    for (int i = 0; i < 4; i++) {
        v[i] = p[i * 32 + lane];
        mx = fmaxf(mx, fmaxf(fmaxf(v[i].x, v[i].y), fmaxf(v[i].z, v[i].w)));
    }
#pragma unroll
    for (int o = 16; o > 0; o >>= 1) mx = fmaxf(mx, __shfl_xor_sync(0xFFFFFFFFu, mx, o));

    float sum = 0.f;
#pragma unroll
    for (int i = 0; i < 4; i++) {
        v[i].x = __expf(v[i].x - mx); v[i].y = __expf(v[i].y - mx);
        v[i].z = __expf(v[i].z - mx); v[i].w = __expf(v[i].w - mx);
        sum += (v[i].x + v[i].y) + (v[i].z + v[i].w);
    }
#pragma unroll
    for (int o = 16; o > 0; o >>= 1) sum += __shfl_xor_sync(0xFFFFFFFFu, sum, o);

    const float inv = 1.0f / sum;
    uint2* ph = (uint2*)(g_w_hi + row * LQ);
    uint2* pl = (uint2*)(g_w_lo + row * LQ);
#pragma unroll
    for (int i = 0; i < 4; i++) {
        v[i].x *= inv; v[i].y *= inv; v[i].z *= inv; v[i].w *= inv;
        uint32_t h01, h23, l01, l23;
        split4(v[i], h01, h23, l01, l23);
        ph[i * 32 + lane] = make_uint2(h01, h23);
        pl[i * 32 + lane] = make_uint2(l01, l23);
    }
}

// ---------------------------------------------------------------------------
extern "C" void kernel_launch(void* const* d_in, const int* in_sizes, int n_in,
                              void* d_out, int out_size)
{
    const float* question = (const float*)d_in[0];
    const float* context  = (const float*)d_in[1];
    if (in_sizes[0] > in_sizes[1]) {
        const float* t = question; question = context; context = t;
    }
    float* out = (float*)d_out;

    // pre-split Q (small, ~6us)
    ba_split_q<<<(size_t)BATCH * LQ * DIM / 4 / 256, 256>>>(question);

    // logits = ctx @ q^T -> g_attn
    ba_mma<true><<<dim3(LQ / 128, LC / 128, BATCH), 256>>>(context, nullptr);
    // softmax -> bf16 hi/lo weights
    ba_softmax<<<BATCH * LC / 8, 256>>>();
    // attn_out = w @ q -> right half of out, + fused ctx copy -> left half
    ba_mma<false><<<dim3(DIM / 128, LC / 128, BATCH), 256>>>(context, out);
}

// round 11
// speedup vs baseline: 1.1611x; 1.1611x over previous
#include <cuda_runtime.h>
#include <cuda_bf16.h>
#include <cstdint>

#define BATCH 16
#define LQ    512
#define LC    2048
#define DIM   1024

// ---------------------------------------------------------------------------
// Device scratch (device-side only; symbols NEVER passed from host)
// ---------------------------------------------------------------------------
__device__ float         g_attn[(size_t)BATCH * LC * LQ];     // fp32 logits
__device__ __nv_bfloat16 g_q_hi[(size_t)BATCH * LQ * DIM];
__device__ __nv_bfloat16 g_q_lo[(size_t)BATCH * LQ * DIM];
__device__ __nv_bfloat16 g_w_hi[(size_t)BATCH * LC * LQ];     // softmax weights
__device__ __nv_bfloat16 g_w_lo[(size_t)BATCH * LC * LQ];

// ---------------------------------------------------------------------------
// helpers
// ---------------------------------------------------------------------------
__device__ __forceinline__ void ldm4(uint32_t a, uint32_t& r0, uint32_t& r1,
                                     uint32_t& r2, uint32_t& r3) {
    asm volatile("ldmatrix.sync.aligned.m8n8.x4.shared.b16 {%0,%1,%2,%3}, [%4];"
                 : "=r"(r0), "=r"(r1), "=r"(r2), "=r"(r3) : "r"(a));
}
__device__ __forceinline__ void ldm4t(uint32_t a, uint32_t& r0, uint32_t& r1,
                                      uint32_t& r2, uint32_t& r3) {
    asm volatile("ldmatrix.sync.aligned.m8n8.x4.trans.shared.b16 {%0,%1,%2,%3}, [%4];"
                 : "=r"(r0), "=r"(r1), "=r"(r2), "=r"(r3) : "r"(a));
}
__device__ __forceinline__ void mma16816(float* c, uint32_t a0, uint32_t a1, uint32_t a2,
                                         uint32_t a3, uint32_t b0, uint32_t b1) {
    asm volatile(
        "mma.sync.aligned.m16n8k16.row.col.f32.bf16.bf16.f32 "
        "{%0,%1,%2,%3}, {%4,%5,%6,%7}, {%8,%9}, {%0,%1,%2,%3};"
        : "+f"(c[0]), "+f"(c[1]), "+f"(c[2]), "+f"(c[3])
        : "r"(a0), "r"(a1), "r"(a2), "r"(a3), "r"(b0), "r"(b1));
}
__device__ __forceinline__ uint32_t smem_u32(const void* p) {
    uint32_t a;
    asm("{ .reg .u64 t; cvta.to.shared.u64 t, %1; cvt.u32.u64 %0, t; }" : "=r"(a) : "l"(p));
    return a;
}
// split float4 into packed bf16 hi pair-words and lo pair-words
__device__ __forceinline__ void split4(float4 v, uint32_t& h01, uint32_t& h23,
                                       uint32_t& l01, uint32_t& l23) {
    __nv_bfloat16 hx = __float2bfloat16(v.x), hy = __float2bfloat16(v.y);
    __nv_bfloat16 hz = __float2bfloat16(v.z), hw = __float2bfloat16(v.w);
    float lx = v.x - __bfloat162float(hx), ly = v.y - __bfloat162float(hy);
    float lz = v.z - __bfloat162float(hz), lw = v.w - __bfloat162float(hw);
    __nv_bfloat162 H0(hx, hy), H1(hz, hw);
    __nv_bfloat162 L0 = __floats2bfloat162_rn(lx, ly), L1 = __floats2bfloat162_rn(lz, lw);
    h01 = *(uint32_t*)&H0; h23 = *(uint32_t*)&H1;
    l01 = *(uint32_t*)&L0; l23 = *(uint32_t*)&L1;
}

// ---------------------------------------------------------------------------
// Q pre-split: fp32 -> bf16 hi/lo (small: ~6us)
// ---------------------------------------------------------------------------
__global__ __launch_bounds__(256)
void ba_split_q(const float* __restrict__ src)
{
    const size_t i = (size_t)blockIdx.x * 256 + threadIdx.x;   // float4 index
    float4 v = ((const float4*)src)[i];
    uint32_t h01, h23, l01, l23;
    split4(v, h01, h23, l01, l23);
    ((uint2*)g_q_hi)[i] = make_uint2(h01, h23);
    ((uint2*)g_q_lo)[i] = make_uint2(l01, l23);
}

// ---------------------------------------------------------------------------
// Split-bf16 mma GEMM (register-prefetch LDG + STS, BK=16, double-buffered
// static smem, CTA 128x128, 8 warps 64x32). __launch_bounds__(256,2) caps the
// kernel at 128 regs so 2 CTAs/SM stay resident (R10 hit 134 regs -> 1 CTA/SM
// and tensor% collapsed; this pin is the fix).
// FIRST : logits[c][q] = ctx(fp32, split in-loop) . q(pre-split)   -> g_attn
// !FIRST: attn [c][d] = w(pre-split) . q(pre-split)  B=[k][n]      -> out right
//         + fused ctx 128x128 tile copy into out LEFT half.
// ---------------------------------------------------------------------------
#define AROWB 48                   // 16 bf16 = 32B + 16B pad (conflict-free)
#define BROWB2 272                 // GEMM2 B rows: 256B + 16B pad

template <bool FIRST>
__global__ __launch_bounds__(256, 2)
void ba_mma(const float* __restrict__ actx, float* __restrict__ gout)
{
    constexpr int KT = FIRST ? DIM : LQ;
    constexpr int NT = KT / 16;
    constexpr int OUTSTRIDE = FIRST ? LQ : 2 * DIM;
    constexpr int OUTOFF    = FIRST ? 0  : DIM;
    constexpr int BHALF = FIRST ? (128 * AROWB) : (16 * BROWB2);   // 6144 / 4352
    constexpr int STAGE = 2 * 128 * AROWB + 2 * BHALF;             // 24576 / 20992
    constexpr int AH = 0, AL = 128 * AROWB, BH = 2 * 128 * AROWB, BL = BH + BHALF;

    __shared__ __align__(16) char sm[2 * STAGE];
    const uint32_t sb = smem_u32(sm);

    const int tid  = threadIdx.x;
    const int lane = tid & 31;
    const int warp = tid >> 5;
    const int wm   = warp & 1;         // m offset 64*wm
    const int wn   = warp >> 1;        // n offset 32*wn
    const int b  = blockIdx.z;
    const int yT = blockIdx.y;
    const int xT = blockIdx.x;

    // DEVICE-SIDE scratch binding
    const float* Abase_f = actx + ((size_t)b * LC + (size_t)yT * 128) * DIM;     // GEMM1 A
    const char*  Awh = (const char*)g_w_hi + ((size_t)b * LC + (size_t)yT * 128) * LQ * 2;
    const char*  Awl = (const char*)g_w_lo + ((size_t)b * LC + (size_t)yT * 128) * LQ * 2;
    const char*  Bqh;
    const char*  Bql;
    if (FIRST) {   // B rows = q index
        Bqh = (const char*)g_q_hi + ((size_t)b * LQ + (size_t)xT * 128) * DIM * 2;
        Bql = (const char*)g_q_lo + ((size_t)b * LQ + (size_t)xT * 128) * DIM * 2;
    } else {       // B = [k=q][n=d]
        Bqh = (const char*)g_q_hi + ((size_t)b * LQ * DIM + (size_t)xT * 128) * 2;
        Bql = (const char*)g_q_lo + ((size_t)b * LQ * DIM + (size_t)xT * 128) * 2;
    }

    // loader coordinates
    const int ar  = tid >> 2, ac  = tid & 3;          // GEMM1 A fp32: rows ar/ar+64, 16B chunk
    const int br  = tid >> 1, bc  = (tid & 1) * 16;   // bf16 [row][32B]: GEMM1 B, GEMM2 A
    const int kr2 = tid >> 4, nc2 = (tid & 15) * 16;  // GEMM2 B: 16 k-rows x 256B

    // prefetch registers
    float4 pa0, pa1;          // GEMM1 A fp32
    uint4  pah, pal;          // GEMM2 A bf16 hi/lo
    uint4  pbh, pbl;          // B bf16 hi/lo (both GEMMs)

    auto ldg_tiles = [&](int kt) {
        if (FIRST) {
            pa0 = *(const float4*)(Abase_f + (size_t)ar * DIM + kt * 16 + ac * 4);
            pa1 = *(const float4*)(Abase_f + (size_t)(ar + 64) * DIM + kt * 16 + ac * 4);
            pbh = *(const uint4*)(Bqh + (size_t)br * (DIM * 2) + kt * 32 + bc);
            pbl = *(const uint4*)(Bql + (size_t)br * (DIM * 2) + kt * 32 + bc);
        } else {
            pah = *(const uint4*)(Awh + (size_t)br * (LQ * 2) + kt * 32 + bc);
            pal = *(const uint4*)(Awl + (size_t)br * (LQ * 2) + kt * 32 + bc);
            pbh = *(const uint4*)(Bqh + (size_t)(kt * 16 + kr2) * (DIM * 2) + nc2);
            pbl = *(const uint4*)(Bql + (size_t)(kt * 16 + kr2) * (DIM * 2) + nc2);
        }
    };
    auto sts_stage = [&](uint32_t s0) {
        if (FIRST) {
            uint32_t h0, h1, l0, l1;
            split4(pa0, h0, h1, l0, l1);
            *(uint2*)(sm + (s0 + AH + ar * AROWB + ac * 8))        = make_uint2(h0, h1);
            *(uint2*)(sm + (s0 + AL + ar * AROWB + ac * 8))        = make_uint2(l0, l1);
            split4(pa1, h0, h1, l0, l1);
            *(uint2*)(sm + (s0 + AH + (ar + 64) * AROWB + ac * 8)) = make_uint2(h0, h1);
            *(uint2*)(sm + (s0 + AL + (ar + 64) * AROWB + ac * 8)) = make_uint2(l0, l1);
            *(uint4*)(sm + (s0 + BH + br * AROWB + bc)) = pbh;
            *(uint4*)(sm + (s0 + BL + br * AROWB + bc)) = pbl;
        } else {
            *(uint4*)(sm + (s0 + AH + br * AROWB + bc))    = pah;
            *(uint4*)(sm + (s0 + AL + br * AROWB + bc))    = pal;
            *(uint4*)(sm + (s0 + BH + kr2 * BROWB2 + nc2)) = pbh;
            *(uint4*)(sm + (s0 + BL + kr2 * BROWB2 + nc2)) = pbl;
        }
    };

    float acc[4][4][4];
#pragma unroll
    for (int m = 0; m < 4; m++)
#pragma unroll
        for (int n = 0; n < 4; n++)
#pragma unroll
            for (int j = 0; j < 4; j++) acc[m][n][j] = 0.f;

    // prologue: stage 0
    ldg_tiles(0);
    sts_stage(0);
    __syncthreads();

    const int lrow = lane & 15;
    const int lkb  = lane & 16;         // second 16B chunk (k+8 / n+8)
    constexpr int I1 = FIRST ? 2 : 1;   // ntile0 second b-reg
    constexpr int J0 = FIRST ? 1 : 2;   // ntile1 first b-reg

    for (int kt = 0; kt < NT; kt++) {
        const uint32_t s0 = (kt & 1) * STAGE;

        if (kt + 1 < NT) ldg_tiles(kt + 1);

        uint32_t ah[4][4], al[4][4];
#pragma unroll
        for (int mt = 0; mt < 4; mt++) {
            uint32_t ra = sb + s0 + AH + (wm * 64 + mt * 16 + lrow) * AROWB + lkb;
            ldm4(ra, ah[mt][0], ah[mt][1], ah[mt][2], ah[mt][3]);
            uint32_t rl = sb + s0 + AL + (wm * 64 + mt * 16 + lrow) * AROWB + lkb;
            ldm4(rl, al[mt][0], al[mt][1], al[mt][2], al[mt][3]);
        }
#pragma unroll
        for (int p = 0; p < 2; p++) {
            uint32_t bh[4], bl[4];
            if (FIRST) {
                uint32_t rb = sb + s0 + BH + (wn * 32 + p * 16 + lrow) * AROWB + lkb;
                ldm4(rb, bh[0], bh[1], bh[2], bh[3]);
                uint32_t rc = sb + s0 + BL + (wn * 32 + p * 16 + lrow) * AROWB + lkb;
                ldm4(rc, bl[0], bl[1], bl[2], bl[3]);
            } else {
                uint32_t rb = sb + s0 + BH + lrow * BROWB2 + (wn * 32 + p * 16) * 2 + lkb;
                ldm4t(rb, bh[0], bh[1], bh[2], bh[3]);
                uint32_t rc = sb + s0 + BL + lrow * BROWB2 + (wn * 32 + p * 16) * 2 + lkb;
                ldm4t(rc, bl[0], bl[1], bl[2], bl[3]);
            }
#pragma unroll
            for (int mt = 0; mt < 4; mt++) {
                mma16816(acc[mt][2 * p],     ah[mt][0], ah[mt][1], ah[mt][2], ah[mt][3], bh[0],  bh[I1]);
                mma16816(acc[mt][2 * p + 1], ah[mt][0], ah[mt][1], ah[mt][2], ah[mt][3], bh[J0], bh[3]);
                mma16816(acc[mt][2 * p],     al[mt][0], al[mt][1], al[mt][2], al[mt][3], bh[0],  bh[I1]);
                mma16816(acc[mt][2 * p + 1], al[mt][0], al[mt][1], al[mt][2], al[mt][3], bh[J0], bh[3]);
                mma16816(acc[mt][2 * p],     ah[mt][0], ah[mt][1], ah[mt][2], ah[mt][3], bl[0],  bl[I1]);
                mma16816(acc[mt][2 * p + 1], ah[mt][0], ah[mt][1], ah[mt][2], ah[mt][3], bl[J0], bl[3]);
            }
        }

        if (kt + 1 < NT) sts_stage(((kt + 1) & 1) * STAGE);
        __syncthreads();
    }

    // epilogue (standard m16n8 C layout)
    float* Cg = FIRST ? (float*)g_attn : gout;
    const size_t rbase = (size_t)b * LC + (size_t)yT * 128 + wm * 64 + (lane >> 2);
    const int    cbase = OUTOFF + xT * 128 + wn * 32 + (lane & 3) * 2;
#pragma unroll
    for (int mt = 0; mt < 4; mt++) {
#pragma unroll
        for (int nt = 0; nt < 4; nt++) {
            size_t r0 = (rbase + mt * 16) * OUTSTRIDE + cbase + nt * 8;
            *(float2*)(Cg + r0)                    = make_float2(acc[mt][nt][0], acc[mt][nt][1]);
            *(float2*)(Cg + r0 + 8ull * OUTSTRIDE) = make_float2(acc[mt][nt][2], acc[mt][nt][3]);
        }
    }

    // fused ctx copy into out LEFT half (GEMM2 only)
    if (!FIRST) {
        const float4* csrc = (const float4*)(actx + ((size_t)b * LC + (size_t)yT * 128) * DIM
                                             + (size_t)xT * 128);
        float4* cdst = (float4*)(gout + ((size_t)b * LC + (size_t)yT * 128) * (2 * DIM)
                                 + (size_t)xT * 128);
        const int crow = tid >> 5;
        const int ccol = tid & 31;
#pragma unroll
        for (int it = 0; it < 16; it++) {
            cdst[(size_t)(crow + it * 8) * (2 * DIM / 4) + ccol] =
                csrc[(size_t)(crow + it * 8) * (DIM / 4) + ccol];
        }
    }
}

// ---------------------------------------------------------------------------
// Warp-per-row softmax over 512 logits: fp32 in (g_attn), bf16 hi/lo out (g_w).
// ---------------------------------------------------------------------------
__global__ __launch_bounds__(256)
void ba_softmax(void)
{
    const int wid = threadIdx.x >> 5, lane = threadIdx.x & 31;
    const size_t row = (size_t)blockIdx.x * 8 + wid;
    const float4* p = (const float4*)(g_attn + row * LQ);

    float4 v[4];
    float mx = -1e30f;
#pragma unroll
    for (int i = 0; i < 4; i++) {
        v[i] = p[i * 32 + lane];
        mx = fmaxf(mx, fmaxf(fmaxf(v[i].x, v[i].y), fmaxf(v[i].z, v[i].w)));
    }
#pragma unroll
    for (int o = 16; o > 0; o >>= 1) mx = fmaxf(mx, __shfl_xor_sync(0xFFFFFFFFu, mx, o));

    float sum = 0.f;
#pragma unroll
    for (int i = 0; i < 4; i++) {
        v[i].x = __expf(v[i].x - mx); v[i].y = __expf(v[i].y - mx);
        v[i].z = __expf(v[i].z - mx); v[i].w = __expf(v[i].w - mx);
        sum += (v[i].x + v[i].y) + (v[i].z + v[i].w);
    }
#pragma unroll
    for (int o = 16; o > 0; o >>= 1) sum += __shfl_xor_sync(0xFFFFFFFFu, sum, o);

    const float inv = 1.0f / sum;
    uint2* ph = (uint2*)(g_w_hi + row * LQ);
    uint2* pl = (uint2*)(g_w_lo + row * LQ);
#pragma unroll
    for (int i = 0; i < 4; i++) {
        v[i].x *= inv; v[i].y *= inv; v[i].z *= inv; v[i].w *= inv;
        uint32_t h01, h23, l01, l23;
        split4(v[i], h01, h23, l01, l23);
        ph[i * 32 + lane] = make_uint2(h01, h23);
        pl[i * 32 + lane] = make_uint2(l01, l23);
    }
}

// ---------------------------------------------------------------------------
extern "C" void kernel_launch(void* const* d_in, const int* in_sizes, int n_in,
                              void* d_out, int out_size)
{
    const float* question = (const float*)d_in[0];
    const float* context  = (const float*)d_in[1];
    if (in_sizes[0] > in_sizes[1]) {
        const float* t = question; question = context; context = t;
    }
    float* out = (float*)d_out;

    // pre-split Q (small, ~6us)
    ba_split_q<<<(size_t)BATCH * LQ * DIM / 4 / 256, 256>>>(question);

    // logits = ctx @ q^T -> g_attn
    ba_mma<true><<<dim3(LQ / 128, LC / 128, BATCH), 256>>>(context, nullptr);
    // softmax -> bf16 hi/lo weights
    ba_softmax<<<BATCH * LC / 8, 256>>>();
    // attn_out = w @ q -> right half of out, + fused ctx copy -> left half
    ba_mma<false><<<dim3(DIM / 128, LC / 128, BATCH), 256>>>(context, out);
}